// round 2
// baseline (speedup 1.0000x reference)
#include <cuda_runtime.h>
#include <math.h>

#define NB   8192
#define LMAX 12
#define TT   10
#define EMB  300
#define CVEC 256
#define HID  256
#define OUTD 512
#define G4   1024   // 4*HID

// ---------------- scratch (static device globals; no allocations) ------------
__device__ float g_e  [TT * NB * EMB];     // interpolated embeddings, t-major (10,B,300)
__device__ float g_cv [TT * NB * CVEC];    // encoder output (10,B,256)
__device__ float g_xg [2][TT * NB * G4];   // precomputed input gates per dir (10,B,1024)
__device__ float g_h  [2][TT * NB * HID];  // hidden states per dir (10,B,256)
__device__ float g_cs [2][NB * HID];       // cell state per dir (B,256)

// ---------------- kernel 1: embedding + bilinear interp ----------------------
__global__ void interp_kernel(const int* __restrict__ words,
                              const int* __restrict__ lengths,
                              const float* __restrict__ emb) {
    int b = blockIdx.x;
    __shared__ int w0s[TT], w1s[TT];
    __shared__ float fs[TT];
    int tid = threadIdx.x;
    if (tid < TT) {
        int L = lengths[b];
        float Lf = (float)(L - 1);
        float pos = (float)tid * Lf / 9.0f;      // identical expr to reference
        int i0 = (int)floorf(pos);
        int i1 = min(i0 + 1, L - 1);
        fs[tid]  = pos - (float)i0;
        w0s[tid] = words[b * LMAX + i0];
        w1s[tid] = words[b * LMAX + i1];
    }
    __syncthreads();
    for (int e = tid; e < TT * EMB; e += blockDim.x) {
        int t = e / EMB, k = e - t * EMB;
        float f = fs[t];
        float v = emb[w0s[t] * EMB + k] * (1.0f - f) + emb[w1s[t] * EMB + k] * f;
        g_e[(t * NB + b) * EMB + k] = v;
    }
}

// ---------------- tiled fp32 GEMM building blocks ----------------------------
#define BM 64
#define BN 64
#define BK 16

// C = relu(A @ W^T + bias); A = g_e (M x 300), C = g_cv (M x 256)
__global__ __launch_bounds__(256)
void gemm_enc(const float* __restrict__ W, const float* __restrict__ bias) {
    const int K = EMB, N = CVEC;
    __shared__ float As[BK][BM + 4];
    __shared__ float Ws[BK][BN + 4];
    int m0 = blockIdx.y * BM, n0 = blockIdx.x * BN;
    int tid = threadIdx.x;
    int tx = tid & 15, ty = tid >> 4;
    int ar = tid >> 2, ac = (tid & 3) * 4;
    float acc[4][4] = {};
    for (int k0 = 0; k0 < K; k0 += BK) {
        float4 av = make_float4(0.f, 0.f, 0.f, 0.f);
        float4 wv = make_float4(0.f, 0.f, 0.f, 0.f);
        if (k0 + ac + 4 <= K) {
            av = *(const float4*)&g_e[(size_t)(m0 + ar) * K + k0 + ac];
            wv = *(const float4*)&W[(size_t)(n0 + ar) * K + k0 + ac];
        }
        As[ac + 0][ar] = av.x; As[ac + 1][ar] = av.y; As[ac + 2][ar] = av.z; As[ac + 3][ar] = av.w;
        Ws[ac + 0][ar] = wv.x; Ws[ac + 1][ar] = wv.y; Ws[ac + 2][ar] = wv.z; Ws[ac + 3][ar] = wv.w;
        __syncthreads();
#pragma unroll
        for (int kk = 0; kk < BK; kk++) {
            float a[4], w[4];
#pragma unroll
            for (int i = 0; i < 4; i++) a[i] = As[kk][ty * 4 + i];
#pragma unroll
            for (int j = 0; j < 4; j++) w[j] = Ws[kk][tx * 4 + j];
#pragma unroll
            for (int i = 0; i < 4; i++)
#pragma unroll
                for (int j = 0; j < 4; j++) acc[i][j] += a[i] * w[j];
        }
        __syncthreads();
    }
#pragma unroll
    for (int i = 0; i < 4; i++) {
        int m = m0 + ty * 4 + i;
#pragma unroll
        for (int j = 0; j < 4; j++) {
            int n = n0 + tx * 4 + j;
            g_cv[(size_t)m * N + n] = fmaxf(acc[i][j] + bias[n], 0.0f);
        }
    }
}

// g_xg[dir] = g_cv @ Wih^T + (b1 + b2);  M x 1024, K = 256
__global__ __launch_bounds__(256)
void gemm_ih(const float* __restrict__ W, const float* __restrict__ b1,
             const float* __restrict__ b2, int dir) {
    const int K = CVEC, N = G4;
    __shared__ float As[BK][BM + 4];
    __shared__ float Ws[BK][BN + 4];
    int m0 = blockIdx.y * BM, n0 = blockIdx.x * BN;
    int tid = threadIdx.x;
    int tx = tid & 15, ty = tid >> 4;
    int ar = tid >> 2, ac = (tid & 3) * 4;
    float acc[4][4] = {};
    for (int k0 = 0; k0 < K; k0 += BK) {
        float4 av = *(const float4*)&g_cv[(size_t)(m0 + ar) * K + k0 + ac];
        float4 wv = *(const float4*)&W[(size_t)(n0 + ar) * K + k0 + ac];
        As[ac + 0][ar] = av.x; As[ac + 1][ar] = av.y; As[ac + 2][ar] = av.z; As[ac + 3][ar] = av.w;
        Ws[ac + 0][ar] = wv.x; Ws[ac + 1][ar] = wv.y; Ws[ac + 2][ar] = wv.z; Ws[ac + 3][ar] = wv.w;
        __syncthreads();
#pragma unroll
        for (int kk = 0; kk < BK; kk++) {
            float a[4], w[4];
#pragma unroll
            for (int i = 0; i < 4; i++) a[i] = As[kk][ty * 4 + i];
#pragma unroll
            for (int j = 0; j < 4; j++) w[j] = Ws[kk][tx * 4 + j];
#pragma unroll
            for (int i = 0; i < 4; i++)
#pragma unroll
                for (int j = 0; j < 4; j++) acc[i][j] += a[i] * w[j];
        }
        __syncthreads();
    }
    float* C = g_xg[dir];
#pragma unroll
    for (int i = 0; i < 4; i++) {
        int m = m0 + ty * 4 + i;
#pragma unroll
        for (int j = 0; j < 4; j++) {
            int n = n0 + tx * 4 + j;
            C[(size_t)m * N + n] = acc[i][j] + b1[n] + b2[n];
        }
    }
}

// out[(b,t,:)] = concat(h_f[t,b], h_b[t,b]) @ out_w^T + out_b;  M x 512, K = 512
__global__ __launch_bounds__(256)
void gemm_out(const float* __restrict__ W, const float* __restrict__ bias,
              float* __restrict__ out) {
    const int K = 2 * HID, N = OUTD;
    __shared__ float As[BK][BM + 4];
    __shared__ float Ws[BK][BN + 4];
    int m0 = blockIdx.y * BM, n0 = blockIdx.x * BN;
    int tid = threadIdx.x;
    int tx = tid & 15, ty = tid >> 4;
    int ar = tid >> 2, ac = (tid & 3) * 4;
    float acc[4][4] = {};
    for (int k0 = 0; k0 < K; k0 += BK) {
        int kidx = k0 + ac;
        const float* src = (kidx < HID) ? g_h[0] : g_h[1];
        float4 av = *(const float4*)&src[(size_t)(m0 + ar) * HID + (kidx & (HID - 1))];
        float4 wv = *(const float4*)&W[(size_t)(n0 + ar) * K + kidx];
        As[ac + 0][ar] = av.x; As[ac + 1][ar] = av.y; As[ac + 2][ar] = av.z; As[ac + 3][ar] = av.w;
        Ws[ac + 0][ar] = wv.x; Ws[ac + 1][ar] = wv.y; Ws[ac + 2][ar] = wv.z; Ws[ac + 3][ar] = wv.w;
        __syncthreads();
#pragma unroll
        for (int kk = 0; kk < BK; kk++) {
            float a[4], w[4];
#pragma unroll
            for (int i = 0; i < 4; i++) a[i] = As[kk][ty * 4 + i];
#pragma unroll
            for (int j = 0; j < 4; j++) w[j] = Ws[kk][tx * 4 + j];
#pragma unroll
            for (int i = 0; i < 4; i++)
#pragma unroll
                for (int j = 0; j < 4; j++) acc[i][j] += a[i] * w[j];
        }
        __syncthreads();
    }
#pragma unroll
    for (int i = 0; i < 4; i++) {
        int m = m0 + ty * 4 + i;   // m = t*NB + b  (t-major)
        int t = m >> 13;           // NB = 8192
        int b = m & (NB - 1);
#pragma unroll
        for (int j = 0; j < 4; j++) {
            int n = n0 + tx * 4 + j;
            out[((size_t)b * TT + t) * OUTD + n] = acc[i][j] + bias[n];
        }
    }
}

// ---------------- fused recurrent GEMM + LSTM cell (both directions) ---------
__global__ __launch_bounds__(256)
void lstm_step(const float* __restrict__ whh_f, const float* __restrict__ whh_b, int s) {
    int dir = blockIdx.z;
    int t = dir ? (TT - 1 - s) : s;
    const float* whh = dir ? whh_b : whh_f;
    const float* xg = g_xg[dir] + (size_t)t * NB * G4;
    float* hout = g_h[dir] + (size_t)t * NB * HID;
    const float* hprev =
        (s > 0) ? (g_h[dir] + (size_t)(dir ? t + 1 : t - 1) * NB * HID) : (const float*)0;
    float* cs = g_cs[dir];

    __shared__ float hs[32][33];
    __shared__ float ws[4][32][33];
    int h0 = blockIdx.x * 32;
    int b0 = blockIdx.y * 32;
    int tid = threadIdx.x;
    int hh = tid & 31, bq = tid >> 5;
    float acc[4][4] = {};   // [batch-sub][gate]

    if (s > 0) {
        int lr = tid >> 3, lc = (tid & 7) * 4;
        for (int k0 = 0; k0 < HID; k0 += 32) {
            float4 hv = *(const float4*)&hprev[(size_t)(b0 + lr) * HID + k0 + lc];
            hs[lr][lc + 0] = hv.x; hs[lr][lc + 1] = hv.y; hs[lr][lc + 2] = hv.z; hs[lr][lc + 3] = hv.w;
#pragma unroll
            for (int g = 0; g < 4; g++) {
                float4 wv = *(const float4*)&whh[(size_t)(g * HID + h0 + lr) * HID + k0 + lc];
                ws[g][lr][lc + 0] = wv.x; ws[g][lr][lc + 1] = wv.y;
                ws[g][lr][lc + 2] = wv.z; ws[g][lr][lc + 3] = wv.w;
            }
            __syncthreads();
#pragma unroll
            for (int kk = 0; kk < 32; kk++) {
                float w4[4];
#pragma unroll
                for (int g = 0; g < 4; g++) w4[g] = ws[g][hh][kk];
#pragma unroll
                for (int m = 0; m < 4; m++) {
                    float hv2 = hs[bq * 4 + m][kk];
#pragma unroll
                    for (int g = 0; g < 4; g++) acc[m][g] += hv2 * w4[g];
                }
            }
            __syncthreads();
        }
    }

#pragma unroll
    for (int m = 0; m < 4; m++) {
        int b = b0 + bq * 4 + m;
        int hi = h0 + hh;
        float gi = acc[m][0] + xg[(size_t)b * G4 + hi];
        float gf = acc[m][1] + xg[(size_t)b * G4 + HID + hi];
        float gg = acc[m][2] + xg[(size_t)b * G4 + 2 * HID + hi];
        float go = acc[m][3] + xg[(size_t)b * G4 + 3 * HID + hi];
        float cp = (s > 0) ? cs[(size_t)b * HID + hi] : 0.0f;
        float ii = 1.0f / (1.0f + expf(-gi));
        float ff = 1.0f / (1.0f + expf(-gf));
        float gt = tanhf(gg);
        float oo = 1.0f / (1.0f + expf(-go));
        float c = ff * cp + ii * gt;
        cs[(size_t)b * HID + hi] = c;
        hout[(size_t)b * HID + hi] = oo * tanhf(c);
    }
}

// ---------------- launcher ---------------------------------------------------
extern "C" void kernel_launch(void* const* d_in, const int* in_sizes, int n_in,
                              void* d_out, int out_size) {
    const int*   words   = (const int*)d_in[0];
    const int*   lengths = (const int*)d_in[1];
    const float* emb     = (const float*)d_in[2];
    const float* enc_w   = (const float*)d_in[3];
    const float* enc_b   = (const float*)d_in[4];
    const float* wih_f   = (const float*)d_in[5];
    const float* whh_f   = (const float*)d_in[6];
    const float* bih_f   = (const float*)d_in[7];
    const float* bhh_f   = (const float*)d_in[8];
    const float* wih_b   = (const float*)d_in[9];
    const float* whh_b   = (const float*)d_in[10];
    const float* bih_b   = (const float*)d_in[11];
    const float* bhh_b   = (const float*)d_in[12];
    const float* out_w   = (const float*)d_in[13];
    const float* out_b   = (const float*)d_in[14];
    float* out = (float*)d_out;

    const int M = TT * NB;  // 81920

    interp_kernel<<<NB, 256>>>(words, lengths, emb);

    dim3 genc(CVEC / BN, M / BM);
    gemm_enc<<<genc, 256>>>(enc_w, enc_b);

    dim3 gih(G4 / BN, M / BM);
    gemm_ih<<<gih, 256>>>(wih_f, bih_f, bhh_f, 0);
    gemm_ih<<<gih, 256>>>(wih_b, bih_b, bhh_b, 1);

    dim3 gstep(HID / 32, NB / 32, 2);
    for (int s = 0; s < TT; s++) {
        lstm_step<<<gstep, 256>>>(whh_f, whh_b, s);
    }

    dim3 gout(OUTD / BN, M / BM);
    gemm_out<<<gout, 256>>>(out_w, out_b, out);
}

// round 5
// speedup vs baseline: 1.2083x; 1.2083x over previous
#include <cuda_runtime.h>
#include <math.h>

#define NB   8192
#define LMAX 12
#define TT   10
#define EMB  300
#define CVEC 256
#define HID  256
#define OUTD 512
#define G4   1024   // 4*HID

#define BM 128
#define BN 128
#define BKT 32

// ---------------- scratch (static device globals; no allocations) ------------
__device__ float g_e  [TT * NB * EMB];     // interpolated embeddings, t-major (10,B,300)
__device__ float g_cv [TT * NB * CVEC];    // encoder output (10,B,256)
__device__ float g_xg [2][TT * NB * G4];   // input gates per dir, GATE-PERMUTED n'=4*hid+gate
__device__ float g_h  [2][TT * NB * HID];  // hidden states per dir (10,B,256)
__device__ float g_cs [2][NB * HID];       // cell state per dir (B,256)

// ---------------- helpers ----------------------------------------------------
__device__ __forceinline__ unsigned f2tf32(float x) {
    unsigned r;
    asm("cvt.rna.tf32.f32 %0, %1;" : "=r"(r) : "f"(x));
    return r;
}

__device__ __forceinline__ void mma_tf32(float* d, const unsigned* a, const unsigned* b) {
    asm volatile(
        "mma.sync.aligned.m16n8k8.row.col.f32.tf32.tf32.f32 "
        "{%0,%1,%2,%3}, {%4,%5,%6,%7}, {%8,%9}, {%0,%1,%2,%3};"
        : "+f"(d[0]), "+f"(d[1]), "+f"(d[2]), "+f"(d[3])
        : "r"(a[0]), "r"(a[1]), "r"(a[2]), "r"(a[3]), "r"(b[0]), "r"(b[1]));
}

// ---------------- kernel 1: embedding + bilinear interp ----------------------
__global__ void interp_kernel(const int* __restrict__ words,
                              const int* __restrict__ lengths,
                              const float* __restrict__ emb) {
    int b = blockIdx.x;
    __shared__ int w0s[TT], w1s[TT];
    __shared__ float fs[TT];
    int tid = threadIdx.x;
    if (tid < TT) {
        int L = lengths[b];
        float Lf = (float)(L - 1);
        float pos = (float)tid * Lf / 9.0f;      // identical expr to reference
        int i0 = (int)floorf(pos);
        int i1 = min(i0 + 1, L - 1);
        fs[tid]  = pos - (float)i0;
        w0s[tid] = words[b * LMAX + i0];
        w1s[tid] = words[b * LMAX + i1];
    }
    __syncthreads();
    for (int e = tid; e < TT * EMB; e += blockDim.x) {
        int t = e / EMB, k = e - t * EMB;
        float f = fs[t];
        float v = emb[w0s[t] * EMB + k] * (1.0f - f) + emb[w1s[t] * EMB + k] * f;
        g_e[(t * NB + b) * EMB + k] = v;
    }
}

// ---------------- generic tf32 mma GEMM --------------------------------------
// mode 0: g_cv = relu(g_e @ enc_w^T + b1)              K=300 N=256
// mode 1: g_xg[dir] = g_cv @ wih^T + (b1+b2), n'-perm  K=256 N=1024
// mode 2: out = concat(g_h0,g_h1) @ out_w^T + b1       K=512 N=512 (scatter)
__global__ __launch_bounds__(256, 1)
void gemm_mma(const float* __restrict__ W, const float* __restrict__ b1,
              const float* __restrict__ b2, float* __restrict__ Cout,
              int mode, int dir) {
    __shared__ unsigned As[BM][BKT + 4];
    __shared__ unsigned Bs[BN][BKT + 4];

    const int K = (mode == 0) ? EMB : (mode == 1 ? CVEC : 2 * HID);
    const int N = (mode == 0) ? CVEC : (mode == 1 ? G4 : OUTD);

    int m0 = blockIdx.y * BM, n0 = blockIdx.x * BN;
    int tid = threadIdx.x;
    int warp = tid >> 5, lane = tid & 31;
    int g = lane >> 2, tg = lane & 3;
    int wm = (warp >> 2) * 64, wn = (warp & 3) * 32;

    int crow = tid >> 1;
    int ccol0 = (tid & 1) * 16;

    float acc[4][4][4] = {};

    for (int k0 = 0; k0 < K; k0 += BKT) {
        // ---- load A tile ----
#pragma unroll
        for (int i = 0; i < 4; i++) {
            int col = ccol0 + i * 4;
            int kk = k0 + col;
            float4 v = make_float4(0.f, 0.f, 0.f, 0.f);
            if (mode == 0) {
                if (kk < EMB)
                    v = *(const float4*)&g_e[(size_t)(m0 + crow) * EMB + kk];
            } else if (mode == 1) {
                v = *(const float4*)&g_cv[(size_t)(m0 + crow) * CVEC + kk];
            } else {
                const float* src = (kk < HID) ? g_h[0] : g_h[1];
                v = *(const float4*)&src[(size_t)(m0 + crow) * HID + (kk & (HID - 1))];
            }
            As[crow][col + 0] = f2tf32(v.x); As[crow][col + 1] = f2tf32(v.y);
            As[crow][col + 2] = f2tf32(v.z); As[crow][col + 3] = f2tf32(v.w);
        }
        // ---- load W tile ----
#pragma unroll
        for (int i = 0; i < 4; i++) {
            int col = ccol0 + i * 4;
            int kk = k0 + col;
            int n = n0 + crow;
            int r = (mode == 1) ? ((n & 3) * HID + (n >> 2)) : n;
            float4 v = make_float4(0.f, 0.f, 0.f, 0.f);
            if (mode != 0 || kk < EMB)
                v = *(const float4*)&W[(size_t)r * K + kk];
            Bs[crow][col + 0] = f2tf32(v.x); Bs[crow][col + 1] = f2tf32(v.y);
            Bs[crow][col + 2] = f2tf32(v.z); Bs[crow][col + 3] = f2tf32(v.w);
        }
        __syncthreads();
#pragma unroll
        for (int ks = 0; ks < BKT; ks += 8) {
            unsigned a[4][4], b[4][2];
#pragma unroll
            for (int mi = 0; mi < 4; mi++) {
                int r = wm + 16 * mi;
                a[mi][0] = As[r + g][ks + tg];
                a[mi][1] = As[r + g + 8][ks + tg];
                a[mi][2] = As[r + g][ks + tg + 4];
                a[mi][3] = As[r + g + 8][ks + tg + 4];
            }
#pragma unroll
            for (int ni = 0; ni < 4; ni++) {
                int r = wn + 8 * ni + g;
                b[ni][0] = Bs[r][ks + tg];
                b[ni][1] = Bs[r][ks + tg + 4];
            }
#pragma unroll
            for (int mi = 0; mi < 4; mi++)
#pragma unroll
                for (int ni = 0; ni < 4; ni++)
                    mma_tf32(acc[mi][ni], a[mi], b[ni]);
        }
        __syncthreads();
    }

    // ---- epilogue ----
#pragma unroll
    for (int mi = 0; mi < 4; mi++) {
        int row = m0 + wm + 16 * mi + g;
#pragma unroll
        for (int ni = 0; ni < 4; ni++) {
            int col = n0 + wn + 8 * ni + 2 * tg;
            float* a4 = acc[mi][ni];
            if (mode == 0) {
                float bb0 = b1[col], bb1 = b1[col + 1];
                g_cv[(size_t)row * N + col]           = fmaxf(a4[0] + bb0, 0.f);
                g_cv[(size_t)row * N + col + 1]       = fmaxf(a4[1] + bb1, 0.f);
                g_cv[(size_t)(row + 8) * N + col]     = fmaxf(a4[2] + bb0, 0.f);
                g_cv[(size_t)(row + 8) * N + col + 1] = fmaxf(a4[3] + bb1, 0.f);
            } else if (mode == 1) {
                int r0 = (col & 3) * HID + (col >> 2);
                int r1 = ((col + 1) & 3) * HID + ((col + 1) >> 2);
                float bb0 = b1[r0] + b2[r0];
                float bb1 = b1[r1] + b2[r1];
                float* C = g_xg[dir];
                C[(size_t)row * N + col]           = a4[0] + bb0;
                C[(size_t)row * N + col + 1]       = a4[1] + bb1;
                C[(size_t)(row + 8) * N + col]     = a4[2] + bb0;
                C[(size_t)(row + 8) * N + col + 1] = a4[3] + bb1;
            } else {
                int t = row >> 13;              // NB = 8192
                int b = row & (NB - 1);
                float bb0 = b1[col], bb1 = b1[col + 1];
                size_t o1 = ((size_t)b * TT + t) * OUTD + col;
                size_t o2 = ((size_t)(b + 8) * TT + t) * OUTD + col;
                Cout[o1]     = a4[0] + bb0;
                Cout[o1 + 1] = a4[1] + bb1;
                Cout[o2]     = a4[2] + bb0;
                Cout[o2 + 1] = a4[3] + bb1;
            }
        }
    }
}

// ---------------- fused recurrent GEMM (tf32 mma) + LSTM cell ----------------
__global__ __launch_bounds__(256, 1)
void lstm_step_mma(const float* __restrict__ whh_f, const float* __restrict__ whh_b, int s) {
    int dir = blockIdx.z;
    int t = dir ? (TT - 1 - s) : s;
    const float* whh = dir ? whh_b : whh_f;
    const float* xg = g_xg[dir] + (size_t)t * NB * G4;
    float* hout = g_h[dir] + (size_t)t * NB * HID;
    const float* hprev = g_h[dir] + (size_t)(dir ? t + 1 : t - 1) * NB * HID;
    float* cs = g_cs[dir];

    __shared__ unsigned As[BM][BKT + 4];
    __shared__ unsigned Bs[BN][BKT + 4];

    int m0 = blockIdx.y * BM, n0 = blockIdx.x * BN;
    int tid = threadIdx.x;
    int warp = tid >> 5, lane = tid & 31;
    int g = lane >> 2, tg = lane & 3;
    int wm = (warp >> 2) * 64, wn = (warp & 3) * 32;

    int crow = tid >> 1;
    int ccol0 = (tid & 1) * 16;

    float acc[4][4][4] = {};

    if (s > 0) {
        for (int k0 = 0; k0 < HID; k0 += BKT) {
#pragma unroll
            for (int i = 0; i < 4; i++) {
                int col = ccol0 + i * 4;
                int kk = k0 + col;
                float4 v = *(const float4*)&hprev[(size_t)(m0 + crow) * HID + kk];
                As[crow][col + 0] = f2tf32(v.x); As[crow][col + 1] = f2tf32(v.y);
                As[crow][col + 2] = f2tf32(v.z); As[crow][col + 3] = f2tf32(v.w);
                int n = n0 + crow;
                int r = (n & 3) * HID + (n >> 2);
                float4 w = *(const float4*)&whh[(size_t)r * HID + kk];
                Bs[crow][col + 0] = f2tf32(w.x); Bs[crow][col + 1] = f2tf32(w.y);
                Bs[crow][col + 2] = f2tf32(w.z); Bs[crow][col + 3] = f2tf32(w.w);
            }
            __syncthreads();
#pragma unroll
            for (int ks = 0; ks < BKT; ks += 8) {
                unsigned a[4][4], b[4][2];
#pragma unroll
                for (int mi = 0; mi < 4; mi++) {
                    int r = wm + 16 * mi;
                    a[mi][0] = As[r + g][ks + tg];
                    a[mi][1] = As[r + g + 8][ks + tg];
                    a[mi][2] = As[r + g][ks + tg + 4];
                    a[mi][3] = As[r + g + 8][ks + tg + 4];
                }
#pragma unroll
                for (int ni = 0; ni < 4; ni++) {
                    int r = wn + 8 * ni + g;
                    b[ni][0] = Bs[r][ks + tg];
                    b[ni][1] = Bs[r][ks + tg + 4];
                }
#pragma unroll
                for (int mi = 0; mi < 4; mi++)
#pragma unroll
                    for (int ni = 0; ni < 4; ni++)
                        mma_tf32(acc[mi][ni], a[mi], b[ni]);
            }
            __syncthreads();
        }
    }

    // ---- fused LSTM cell epilogue ----
    // columns are gate-permuted: n' = 4*hid + gate. Lane pair (tg, tg^1)
    // exchanges halves so each lane owns all 4 gates of one (b, hid).
#pragma unroll
    for (int mi = 0; mi < 4; mi++) {
#pragma unroll
        for (int ni = 0; ni < 4; ni++) {
            float* a4 = acc[mi][ni];
            float s0 = __shfl_xor_sync(0xffffffffu, a4[0], 1);
            float s1 = __shfl_xor_sync(0xffffffffu, a4[1], 1);
            float s2 = __shfl_xor_sync(0xffffffffu, a4[2], 1);
            float s3 = __shfl_xor_sync(0xffffffffu, a4[3], 1);
            int odd = tg & 1;
            int j = ((n0 + wn + 8 * ni) >> 2) + (tg >> 1);   // hidden index 0..255
            int b = m0 + wm + 16 * mi + g + (odd ? 8 : 0);
            float gi, gf, gg, go;
            if (!odd) { gi = a4[0]; gf = a4[1]; gg = s0;   go = s1;   }
            else      { gi = s2;    gf = s3;    gg = a4[2]; go = a4[3]; }
            float4 xv = *(const float4*)&xg[(size_t)b * G4 + 4 * j];
            gi += xv.x; gf += xv.y; gg += xv.z; go += xv.w;
            float cp = (s > 0) ? cs[(size_t)b * HID + j] : 0.0f;
            float ii = 1.0f / (1.0f + expf(-gi));
            float ff = 1.0f / (1.0f + expf(-gf));
            float gt = tanhf(gg);
            float oo = 1.0f / (1.0f + expf(-go));
            float c = ff * cp + ii * gt;
            cs[(size_t)b * HID + j] = c;
            hout[(size_t)b * HID + j] = oo * tanhf(c);
        }
    }
}

// ---------------- launcher ---------------------------------------------------
extern "C" void kernel_launch(void* const* d_in, const int* in_sizes, int n_in,
                              void* d_out, int out_size) {
    const int*   words   = (const int*)d_in[0];
    const int*   lengths = (const int*)d_in[1];
    const float* emb     = (const float*)d_in[2];
    const float* enc_w   = (const float*)d_in[3];
    const float* enc_b   = (const float*)d_in[4];
    const float* wih_f   = (const float*)d_in[5];
    const float* whh_f   = (const float*)d_in[6];
    const float* bih_f   = (const float*)d_in[7];
    const float* bhh_f   = (const float*)d_in[8];
    const float* wih_b   = (const float*)d_in[9];
    const float* whh_b   = (const float*)d_in[10];
    const float* bih_b   = (const float*)d_in[11];
    const float* bhh_b   = (const float*)d_in[12];
    const float* out_w   = (const float*)d_in[13];
    const float* out_b   = (const float*)d_in[14];
    float* out = (float*)d_out;

    const int M = TT * NB;  // 81920

    interp_kernel<<<NB, 256>>>(words, lengths, emb);

    gemm_mma<<<dim3(CVEC / BN, M / BM), 256>>>(enc_w, enc_b, (const float*)0,
                                               (float*)0, 0, 0);
    gemm_mma<<<dim3(G4 / BN, M / BM), 256>>>(wih_f, bih_f, bhh_f, (float*)0, 1, 0);
    gemm_mma<<<dim3(G4 / BN, M / BM), 256>>>(wih_b, bih_b, bhh_b, (float*)0, 1, 1);

    for (int s = 0; s < TT; s++) {
        lstm_step_mma<<<dim3(G4 / BN, NB / BM, 2), 256>>>(whh_f, whh_b, s);
    }

    gemm_mma<<<dim3(OUTD / BN, M / BM), 256>>>(out_w, out_b, (const float*)0, out, 2, 0);
}

// round 14
// speedup vs baseline: 1.8619x; 1.5409x over previous
#include <cuda_runtime.h>
#include <math.h>
#include <stdint.h>

#define NB   8192
#define LMAX 12
#define TT   10
#define EMB  300
#define EMBP 320      // padded to multiple of 32
#define CVEC 256
#define HID  256
#define OUTD 512
#define G4   1024     // 4*HID

#define BM 128
#define BN 128
#define BKT 16
#define SPAD 4
#define TILE_F (BKT + SPAD)
// static smem: As[2][BM][TILE_F] + Bs[2][BN][TILE_F] = 40960 bytes (< 48KB)

// ---------------- scratch (static device globals; no allocations) ------------
__device__ __align__(128) float g_e   [TT * NB * EMBP];     // tf32-rounded, padded
__device__ __align__(128) float g_cv  [TT * NB * CVEC];     // tf32-rounded
__device__ __align__(128) float g_xg  [2][TT * NB * G4];    // fp32, gate-permuted n'=4*hid+gate
__device__ __align__(128) float g_hcat[TT * NB * 2 * HID];  // tf32-rounded; [t][b][dir*256+j]
__device__ __align__(128) float g_cs  [2][NB * HID];        // fp32 cell state
// pre-rounded / pre-permuted weights
__device__ __align__(128) float w_enc_t[CVEC * EMBP];
__device__ __align__(128) float w_ih_t [2][G4 * CVEC];
__device__ __align__(128) float w_hh_t [2][G4 * HID];
__device__ __align__(128) float w_out_t[OUTD * 2 * HID];
__device__ __align__(128) float bias_comb[2][G4];

// ---------------- helpers ----------------------------------------------------
__device__ __forceinline__ float f2tf32f(float x) {
    unsigned r;
    asm("cvt.rna.tf32.f32 %0, %1;" : "=r"(r) : "f"(x));
    return __uint_as_float(r);
}

__device__ __forceinline__ void mma_tf32(float* d, const unsigned* a, const unsigned* b) {
    asm volatile(
        "mma.sync.aligned.m16n8k8.row.col.f32.tf32.tf32.f32 "
        "{%0,%1,%2,%3}, {%4,%5,%6,%7}, {%8,%9}, {%0,%1,%2,%3};"
        : "+f"(d[0]), "+f"(d[1]), "+f"(d[2]), "+f"(d[3])
        : "r"(a[0]), "r"(a[1]), "r"(a[2]), "r"(a[3]), "r"(b[0]), "r"(b[1]));
}

__device__ __forceinline__ void cp16(void* smem_dst, const void* gsrc) {
    uint32_t d = (uint32_t)__cvta_generic_to_shared(smem_dst);
    asm volatile("cp.async.cg.shared.global [%0], [%1], 16;\n" :: "r"(d), "l"(gsrc));
}
__device__ __forceinline__ void cp_commit() { asm volatile("cp.async.commit_group;\n"); }
__device__ __forceinline__ void cp_wait1()  { asm volatile("cp.async.wait_group 1;\n"); }

// ---------------- prep kernels (tiny; run inside graph each call) -------------
__global__ void prep_enc(const float* __restrict__ w) {
    int n = blockIdx.x;
    for (int k = threadIdx.x; k < EMBP; k += blockDim.x)
        w_enc_t[n * EMBP + k] = (k < EMB) ? f2tf32f(w[n * EMB + k]) : 0.0f;
}
__global__ void prep_ih(const float* __restrict__ wf, const float* __restrict__ wb,
                        const float* __restrict__ b1f, const float* __restrict__ b2f,
                        const float* __restrict__ b1b, const float* __restrict__ b2b) {
    int np = blockIdx.x, dir = blockIdx.y;
    int r = (np & 3) * HID + (np >> 2);
    const float* w = dir ? wb : wf;
    for (int k = threadIdx.x; k < CVEC; k += blockDim.x)
        w_ih_t[dir][np * CVEC + k] = f2tf32f(w[r * CVEC + k]);
    if (threadIdx.x == 0)
        bias_comb[dir][np] = dir ? (b1b[r] + b2b[r]) : (b1f[r] + b2f[r]);
}
__global__ void prep_hh(const float* __restrict__ wf, const float* __restrict__ wb) {
    int np = blockIdx.x, dir = blockIdx.y;
    int r = (np & 3) * HID + (np >> 2);
    const float* w = dir ? wb : wf;
    for (int k = threadIdx.x; k < HID; k += blockDim.x)
        w_hh_t[dir][np * HID + k] = f2tf32f(w[r * HID + k]);
}
__global__ void prep_out(const float* __restrict__ w) {
    int n = blockIdx.x;
    for (int k = threadIdx.x; k < 2 * HID; k += blockDim.x)
        w_out_t[n * 2 * HID + k] = f2tf32f(w[n * 2 * HID + k]);
}

// ---------------- kernel: embedding + bilinear interp (tf32-rounded, padded) --
__global__ void interp_kernel(const int* __restrict__ words,
                              const int* __restrict__ lengths,
                              const float* __restrict__ emb) {
    int b = blockIdx.x;
    __shared__ int w0s[TT], w1s[TT];
    __shared__ float fs[TT];
    int tid = threadIdx.x;
    if (tid < TT) {
        int L = lengths[b];
        float Lf = (float)(L - 1);
        float pos = (float)tid * Lf / 9.0f;      // identical expr to reference
        int i0 = (int)floorf(pos);
        int i1 = min(i0 + 1, L - 1);
        fs[tid]  = pos - (float)i0;
        w0s[tid] = words[b * LMAX + i0];
        w1s[tid] = words[b * LMAX + i1];
    }
    __syncthreads();
    for (int e = tid; e < TT * EMBP; e += blockDim.x) {
        int t = e / EMBP, k = e - t * EMBP;
        float v = 0.0f;
        if (k < EMB) {
            float f = fs[t];
            v = f2tf32f(emb[w0s[t] * EMB + k] * (1.0f - f) + emb[w1s[t] * EMB + k] * f);
        }
        g_e[(size_t)(t * NB + b) * EMBP + k] = v;
    }
}

// ---------------- pipelined tf32 mma GEMM (static smem, <=48KB) ---------------
// MODE 0: g_cv = tf32(relu(g_e @ w_enc_t^T + bias))        K=320 N=256
// MODE 1: g_xg[dir] = g_cv @ w_ih_t[dir]^T + bias_comb     K=256 N=1024
//         (bias/Cout params IGNORED for MODE 1; device globals resolved in-kernel)
// MODE 2: out = g_hcat @ w_out_t^T + bias  (scatter)       K=512 N=512
template <int MODE>
__global__ __launch_bounds__(256)
void gemm_tc(const float* __restrict__ bias_in, float* __restrict__ Cout, int dir) {
    constexpr int K = (MODE == 0) ? EMBP : (MODE == 1 ? CVEC : 2 * HID);
    constexpr int N = (MODE == 0) ? CVEC : (MODE == 1 ? G4 : OUTD);
    constexpr int NIT = K / BKT;

    __shared__ __align__(16) float As[2][BM][TILE_F];
    __shared__ __align__(16) float Bs[2][BN][TILE_F];

    const float* A  = (MODE == 0) ? g_e : (MODE == 1 ? g_cv : g_hcat);
    const float* Wt = (MODE == 0) ? w_enc_t : (MODE == 1 ? w_ih_t[dir] : w_out_t);
    // device-side resolution of device globals (host cannot pass their addresses)
    const float* bias = (MODE == 1) ? bias_comb[dir] : bias_in;
    float* C1 = (MODE == 1) ? g_xg[dir] : Cout;
    const int lda = K;

    int m0 = blockIdx.y * BM, n0 = blockIdx.x * BN;
    int tid = threadIdx.x;
    int lrow = tid >> 2, lcol = (tid & 3) * 4;     // 64 rows x 16 cols per pass
    const float* Abase = A + (size_t)(m0 + lrow) * lda + lcol;
    const float* Bbase = Wt + (size_t)(n0 + lrow) * K + lcol;

    auto load_tile = [&](int buf, int k0) {
#pragma unroll
        for (int i = 0; i < 2; i++) {
            cp16(&As[buf][lrow + 64 * i][lcol], Abase + (size_t)(64 * i) * lda + k0);
            cp16(&Bs[buf][lrow + 64 * i][lcol], Bbase + (size_t)(64 * i) * K + k0);
        }
    };

    int warp = tid >> 5, lane = tid & 31;
    int g = lane >> 2, tg = lane & 3;
    int wm = (warp >> 2) * 64, wn = (warp & 3) * 32;

    float acc[4][4][4] = {};

    load_tile(0, 0);
    cp_commit();

    for (int it = 0; it < NIT; ++it) {
        if (it + 1 < NIT) load_tile((it + 1) & 1, (it + 1) * BKT);
        cp_commit();
        cp_wait1();
        __syncthreads();
        int buf = it & 1;
#pragma unroll
        for (int ks = 0; ks < BKT; ks += 8) {
            unsigned a[4][4], b[4][2];
#pragma unroll
            for (int mi = 0; mi < 4; mi++) {
                int r = wm + 16 * mi;
                a[mi][0] = __float_as_uint(As[buf][r + g][ks + tg]);
                a[mi][1] = __float_as_uint(As[buf][r + g + 8][ks + tg]);
                a[mi][2] = __float_as_uint(As[buf][r + g][ks + tg + 4]);
                a[mi][3] = __float_as_uint(As[buf][r + g + 8][ks + tg + 4]);
            }
#pragma unroll
            for (int ni = 0; ni < 4; ni++) {
                int r = wn + 8 * ni + g;
                b[ni][0] = __float_as_uint(Bs[buf][r][ks + tg]);
                b[ni][1] = __float_as_uint(Bs[buf][r][ks + tg + 4]);
            }
#pragma unroll
            for (int mi = 0; mi < 4; mi++)
#pragma unroll
                for (int ni = 0; ni < 4; ni++)
                    mma_tf32(acc[mi][ni], a[mi], b[ni]);
        }
        __syncthreads();
    }

    // ---- epilogue ----
#pragma unroll
    for (int mi = 0; mi < 4; mi++) {
        int row = m0 + wm + 16 * mi + g;
#pragma unroll
        for (int ni = 0; ni < 4; ni++) {
            int col = n0 + wn + 8 * ni + 2 * tg;
            float* a4 = acc[mi][ni];
            float bb0 = bias[col], bb1 = bias[col + 1];
            if (MODE == 0) {
                g_cv[(size_t)row * N + col]           = f2tf32f(fmaxf(a4[0] + bb0, 0.f));
                g_cv[(size_t)row * N + col + 1]       = f2tf32f(fmaxf(a4[1] + bb1, 0.f));
                g_cv[(size_t)(row + 8) * N + col]     = f2tf32f(fmaxf(a4[2] + bb0, 0.f));
                g_cv[(size_t)(row + 8) * N + col + 1] = f2tf32f(fmaxf(a4[3] + bb1, 0.f));
            } else if (MODE == 1) {
                C1[(size_t)row * N + col]           = a4[0] + bb0;
                C1[(size_t)row * N + col + 1]       = a4[1] + bb1;
                C1[(size_t)(row + 8) * N + col]     = a4[2] + bb0;
                C1[(size_t)(row + 8) * N + col + 1] = a4[3] + bb1;
            } else {
                int t = row >> 13;              // NB = 8192
                int b = row & (NB - 1);
                size_t o1 = ((size_t)b * TT + t) * OUTD + col;
                size_t o2 = ((size_t)(b + 8) * TT + t) * OUTD + col;
                C1[o1]     = a4[0] + bb0;
                C1[o1 + 1] = a4[1] + bb1;
                C1[o2]     = a4[2] + bb0;
                C1[o2 + 1] = a4[3] + bb1;
            }
        }
    }
}

// ---------------- fused recurrent GEMM (pipelined tf32 mma) + LSTM cell -------
__global__ __launch_bounds__(256)
void lstm_step_mma(int s) {
    int dir = blockIdx.z;
    int t = dir ? (TT - 1 - s) : s;
    int tprev = dir ? t + 1 : t - 1;
    const float* xg = g_xg[dir] + (size_t)t * NB * G4;
    float* hout = g_hcat + (size_t)t * NB * (2 * HID) + dir * HID;
    float* cs = g_cs[dir];

    __shared__ __align__(16) float As[2][BM][TILE_F];
    __shared__ __align__(16) float Bs[2][BN][TILE_F];

    int m0 = blockIdx.y * BM, n0 = blockIdx.x * BN;
    int tid = threadIdx.x;
    int warp = tid >> 5, lane = tid & 31;
    int g = lane >> 2, tg = lane & 3;
    int wm = (warp >> 2) * 64, wn = (warp & 3) * 32;

    float acc[4][4][4] = {};

    if (s > 0) {
        const float* A = g_hcat + (size_t)tprev * NB * (2 * HID) + dir * HID;
        const float* Wt = w_hh_t[dir];
        const int lda = 2 * HID;
        int lrow = tid >> 2, lcol = (tid & 3) * 4;
        const float* Abase = A + (size_t)(m0 + lrow) * lda + lcol;
        const float* Bbase = Wt + (size_t)(n0 + lrow) * HID + lcol;

        auto load_tile = [&](int buf, int k0) {
#pragma unroll
            for (int i = 0; i < 2; i++) {
                cp16(&As[buf][lrow + 64 * i][lcol], Abase + (size_t)(64 * i) * lda + k0);
                cp16(&Bs[buf][lrow + 64 * i][lcol], Bbase + (size_t)(64 * i) * HID + k0);
            }
        };
        constexpr int NIT = HID / BKT;
        load_tile(0, 0);
        cp_commit();
        for (int it = 0; it < NIT; ++it) {
            if (it + 1 < NIT) load_tile((it + 1) & 1, (it + 1) * BKT);
            cp_commit();
            cp_wait1();
            __syncthreads();
            int buf = it & 1;
#pragma unroll
            for (int ks = 0; ks < BKT; ks += 8) {
                unsigned a[4][4], b[4][2];
#pragma unroll
                for (int mi = 0; mi < 4; mi++) {
                    int r = wm + 16 * mi;
                    a[mi][0] = __float_as_uint(As[buf][r + g][ks + tg]);
                    a[mi][1] = __float_as_uint(As[buf][r + g + 8][ks + tg]);
                    a[mi][2] = __float_as_uint(As[buf][r + g][ks + tg + 4]);
                    a[mi][3] = __float_as_uint(As[buf][r + g + 8][ks + tg + 4]);
                }
#pragma unroll
                for (int ni = 0; ni < 4; ni++) {
                    int r = wn + 8 * ni + g;
                    b[ni][0] = __float_as_uint(Bs[buf][r][ks + tg]);
                    b[ni][1] = __float_as_uint(Bs[buf][r][ks + tg + 4]);
                }
#pragma unroll
                for (int mi = 0; mi < 4; mi++)
#pragma unroll
                    for (int ni = 0; ni < 4; ni++)
                        mma_tf32(acc[mi][ni], a[mi], b[ni]);
            }
            __syncthreads();
        }
    }

    // ---- fused LSTM cell epilogue (gate-permuted columns n'=4*hid+gate) ------
#pragma unroll
    for (int mi = 0; mi < 4; mi++) {
#pragma unroll
        for (int ni = 0; ni < 4; ni++) {
            float* a4 = acc[mi][ni];
            float s0 = __shfl_xor_sync(0xffffffffu, a4[0], 1);
            float s1 = __shfl_xor_sync(0xffffffffu, a4[1], 1);
            float s2 = __shfl_xor_sync(0xffffffffu, a4[2], 1);
            float s3 = __shfl_xor_sync(0xffffffffu, a4[3], 1);
            int odd = tg & 1;
            int j = ((n0 + wn + 8 * ni) >> 2) + (tg >> 1);   // hidden index 0..255
            int b = m0 + wm + 16 * mi + g + (odd ? 8 : 0);
            float gi, gf, gg, go;
            if (!odd) { gi = a4[0]; gf = a4[1]; gg = s0;    go = s1;    }
            else      { gi = s2;    gf = s3;    gg = a4[2]; go = a4[3]; }
            float4 xv = *(const float4*)&xg[(size_t)b * G4 + 4 * j];
            gi += xv.x; gf += xv.y; gg += xv.z; go += xv.w;
            float cp = (s > 0) ? cs[(size_t)b * HID + j] : 0.0f;
            float ii = 1.0f / (1.0f + expf(-gi));
            float ff = 1.0f / (1.0f + expf(-gf));
            float gt = tanhf(gg);
            float oo = 1.0f / (1.0f + expf(-go));
            float c = ff * cp + ii * gt;
            cs[(size_t)b * HID + j] = c;
            hout[(size_t)b * (2 * HID) + j] = f2tf32f(oo * tanhf(c));
        }
    }
}

// ---------------- launcher ---------------------------------------------------
extern "C" void kernel_launch(void* const* d_in, const int* in_sizes, int n_in,
                              void* d_out, int out_size) {
    const int*   words   = (const int*)d_in[0];
    const int*   lengths = (const int*)d_in[1];
    const float* emb     = (const float*)d_in[2];
    const float* enc_w   = (const float*)d_in[3];
    const float* enc_b   = (const float*)d_in[4];
    const float* wih_f   = (const float*)d_in[5];
    const float* whh_f   = (const float*)d_in[6];
    const float* bih_f   = (const float*)d_in[7];
    const float* bhh_f   = (const float*)d_in[8];
    const float* wih_b   = (const float*)d_in[9];
    const float* whh_b   = (const float*)d_in[10];
    const float* bih_b   = (const float*)d_in[11];
    const float* bhh_b   = (const float*)d_in[12];
    const float* out_w   = (const float*)d_in[13];
    const float* out_b   = (const float*)d_in[14];
    float* out = (float*)d_out;

    const int M = TT * NB;  // 81920

    prep_enc<<<CVEC, 256>>>(enc_w);
    prep_ih<<<dim3(G4, 2), 256>>>(wih_f, wih_b, bih_f, bhh_f, bih_b, bhh_b);
    prep_hh<<<dim3(G4, 2), 256>>>(whh_f, whh_b);
    prep_out<<<OUTD, 256>>>(out_w);

    interp_kernel<<<NB, 256>>>(words, lengths, emb);

    gemm_tc<0><<<dim3(CVEC / BN, M / BM), 256>>>(enc_b, (float*)0, 0);
    gemm_tc<1><<<dim3(G4 / BN, M / BM), 256>>>((const float*)0, (float*)0, 0);
    gemm_tc<1><<<dim3(G4 / BN, M / BM), 256>>>((const float*)0, (float*)0, 1);

    for (int s = 0; s < TT; s++) {
        lstm_step_mma<<<dim3(G4 / BN, NB / BM, 2), 256>>>(s);
    }

    gemm_tc<2><<<dim3(OUTD / BN, M / BM), 256>>>(out_b, out, 0);
}